// round 6
// baseline (speedup 1.0000x reference)
#include <cuda_runtime.h>
#include <cuda_fp16.h>

// ============================================================================
// GCNMultiRegressor — layer-2 collapsed; fp16 xs (aligned 256B rows, LDG.64
// gathers); three-way stream fork under graph capture:
//   s1: gemm1 (xs = feat@W1, fp16)            [input-only]
//   s0: zero -> build -> c (inline norm_in)
//   s2: norms (tables for agg)                [after build]
//   join -> agg1 (fused relu + layer-2 collapse) -> final
// ============================================================================

#define NMAX 50048
#define HD 96
#define NW2P 64          // half2 words per row (256 B, 128-aligned; 48 used)
#define CAP 64

__device__ int     g_cnt_in[NMAX];
__device__ int     g_cnt_out[NMAX];
__device__ int     g_bucket[(size_t)NMAX * CAP];
__device__ float   g_norm_in[NMAX];
__device__ float   g_norm_out[NMAX];
__device__ float   g_c[NMAX];
__device__ __half2 g_xs[(size_t)NMAX * NW2P];
__device__ float   g_colvec[HD];

// --- capture-fork resources (created once at load; no device mem alloc) ----
static cudaStream_t g_s1, g_s2;
static cudaEvent_t  g_e0, g_e1, g_eb, g_en;
namespace {
struct StreamInit {
    StreamInit() {
        cudaStreamCreateWithFlags(&g_s1, cudaStreamNonBlocking);
        cudaStreamCreateWithFlags(&g_s2, cudaStreamNonBlocking);
        cudaEventCreateWithFlags(&g_e0, cudaEventDisableTiming);
        cudaEventCreateWithFlags(&g_e1, cudaEventDisableTiming);
        cudaEventCreateWithFlags(&g_eb, cudaEventDisableTiming);
        cudaEventCreateWithFlags(&g_en, cudaEventDisableTiming);
    }
};
StreamInit g_stream_init;
}

// ---------------------------------------------------------------------------
__global__ void k_zero(int n) {
    int i = blockIdx.x * blockDim.x + threadIdx.x;
    if (i < n) { g_cnt_in[i] = 0; g_cnt_out[i] = 0; g_c[i] = 0.0f; }
    if (i < HD) g_colvec[i] = 0.0f;
}

__global__ void k_build(const int* __restrict__ src, const int* __restrict__ dst, int e) {
    int i = blockIdx.x * blockDim.x + threadIdx.x;
    if (i < e) {
        int d = dst[i];
        int p = atomicAdd(&g_cnt_in[d], 1);
        if (p < CAP) g_bucket[(size_t)d * CAP + p] = src[i];
        atomicAdd(&g_cnt_out[src[i]], 1);
    }
}

__global__ void k_norms(int n) {
    int i = blockIdx.x * blockDim.x + threadIdx.x;
    if (i < n) {
        int di = g_cnt_in[i], dq = g_cnt_out[i];
        g_norm_in[i]  = rsqrtf((float)(di > 1 ? di : 1));
        g_norm_out[i] = rsqrtf((float)(dq > 1 ? dq : 1));
    }
}

// c[src] += norm_in[dst], norm_in computed inline (no table dependency).
__global__ void k_c(const int* __restrict__ src, const int* __restrict__ dst, int e) {
    int i = blockIdx.x * blockDim.x + threadIdx.x;
    if (i < e) {
        int cin = g_cnt_in[dst[i]];
        float ni = rsqrtf((float)(cin > 1 ? cin : 1));
        atomicAdd(&g_c[src[i]], ni);
    }
}

// xs = feat @ W1 -> fp16 (plain layout: word w = cols 2w,2w+1). R2 core.
__global__ void k_gemm1(const float* __restrict__ X, const float* __restrict__ W, int n) {
    __shared__ float sW[HD * HD];   // 36 KB
    __shared__ float sX[32 * HD];   // 12 KB
    int tid = threadIdx.x;
    int n0  = blockIdx.x * 32;
    for (int i = tid; i < HD * HD; i += 256) sW[i] = W[i];
    for (int i = tid; i < 32 * HD; i += 256) {
        int nn = n0 + (i / HD);
        sX[i] = (nn < n) ? X[(size_t)nn * HD + (i % HD)] : 0.f;
    }
    __syncthreads();
    int tx = tid & 31, ty = tid >> 5;
    float acc[4][3] = {};
#pragma unroll 8
    for (int k = 0; k < HD; k++) {
        float w0 = sW[k * HD + tx];
        float w1 = sW[k * HD + tx + 32];
        float w2 = sW[k * HD + tx + 64];
#pragma unroll
        for (int j = 0; j < 4; j++) {
            float xv = sX[(ty + 8 * j) * HD + k];
            acc[j][0] = fmaf(xv, w0, acc[j][0]);
            acc[j][1] = fmaf(xv, w1, acc[j][1]);
            acc[j][2] = fmaf(xv, w2, acc[j][2]);
        }
    }
#pragma unroll
    for (int j = 0; j < 4; j++) {
        int nn = n0 + ty + 8 * j;               // warp-uniform guard
        if (nn < n) {
            float v0 = acc[j][0], v1 = acc[j][1], v2 = acc[j][2];
            float p0 = __shfl_down_sync(0xffffffffu, v0, 1);
            float p1 = __shfl_down_sync(0xffffffffu, v1, 1);
            float p2 = __shfl_down_sync(0xffffffffu, v2, 1);
            if ((tx & 1) == 0) {
                __half2* o = g_xs + (size_t)nn * NW2P;
                int h = tx >> 1;                 // 0..15
                o[h]      = __floats2half2_rn(v0, p0);   // cols 2h,2h+1
                o[16 + h] = __floats2half2_rn(v1, p1);   // cols 32+2h,33+2h
                o[32 + h] = __floats2half2_rn(v2, p2);   // cols 64+2h,65+2h
            }
        }
    }
}

// Warp-per-node aggregation: one LDG.64 per lane per neighbor row
// (lane<24 covers 192B row; lanes 24-31 duplicate low sectors, masked out).
// Fused relu + layer-2 collapse into colvec.
__global__ void k_agg1(const float* __restrict__ b1v, int n) {
    __shared__ float scol[HD];
    int tid = threadIdx.x, lane = tid & 31, wid = tid >> 5;
    if (tid < HD) scol[tid] = 0.0f;
    __syncthreads();

    bool act = lane < 24;
    int  el  = act ? lane : (lane - 24);     // effective lane for loads
    int  cb  = act ? 4 * lane : 0;           // column base (guard OOB)
    float bb0 = b1v[cb], bb1 = b1v[cb + 1], bb2 = b1v[cb + 2], bb3 = b1v[cb + 3];
    float c0 = 0.f, c1 = 0.f, c2 = 0.f, c3 = 0.f;

    int wpb  = blockDim.x >> 5;
    int totw = gridDim.x * wpb;
    for (int node = blockIdx.x * wpb + wid; node < n; node += totw) {
        int d = g_cnt_in[node];
        if (d > CAP) d = CAP;
        const int* __restrict__ lst = g_bucket + (size_t)node * CAP;
        float a0 = 0.f, a1 = 0.f, a2 = 0.f, a3 = 0.f;
        int j = 0;
        for (; j + 4 <= d; j += 4) {
            int4 q = *(const int4*)(lst + j);
#pragma unroll
            for (int t = 0; t < 4; t++) {
                int s = (t == 0) ? q.x : (t == 1) ? q.y : (t == 2) ? q.z : q.w;
                float f = g_norm_out[s];
                uint2 v = ((const uint2*)(g_xs + (size_t)s * NW2P))[el];
                float2 f01 = __half22float2(*(__half2*)&v.x);
                float2 f23 = __half22float2(*(__half2*)&v.y);
                a0 = fmaf(f, f01.x, a0);
                a1 = fmaf(f, f01.y, a1);
                a2 = fmaf(f, f23.x, a2);
                a3 = fmaf(f, f23.y, a3);
            }
        }
        for (; j < d; j++) {
            int s = lst[j];
            float f = g_norm_out[s];
            uint2 v = ((const uint2*)(g_xs + (size_t)s * NW2P))[el];
            float2 f01 = __half22float2(*(__half2*)&v.x);
            float2 f23 = __half22float2(*(__half2*)&v.y);
            a0 = fmaf(f, f01.x, a0);
            a1 = fmaf(f, f01.y, a1);
            a2 = fmaf(f, f23.x, a2);
            a3 = fmaf(f, f23.y, a3);
        }
        float ni = g_norm_in[node];
        float w  = g_norm_out[node] * g_c[node];
        c0 = fmaf(w, fmaxf(fmaf(ni, a0, bb0), 0.f), c0);
        c1 = fmaf(w, fmaxf(fmaf(ni, a1, bb1), 0.f), c1);
        c2 = fmaf(w, fmaxf(fmaf(ni, a2, bb2), 0.f), c2);
        c3 = fmaf(w, fmaxf(fmaf(ni, a3, bb3), 0.f), c3);
    }
    if (act) {
        atomicAdd(&scol[cb],     c0);
        atomicAdd(&scol[cb + 1], c1);
        atomicAdd(&scol[cb + 2], c2);
        atomicAdd(&scol[cb + 3], c3);
    }
    __syncthreads();
    if (tid < HD) atomicAdd(&g_colvec[tid], scol[tid]);
}

// hg = colvec/N @ W2 + b2 ; out = hg @ Wr^T + br
__global__ void k_final(const float* __restrict__ W2, const float* __restrict__ b2,
                        const float* __restrict__ Wr, const float* __restrict__ br,
                        float* __restrict__ out, int n) {
    __shared__ float hg[HD];
    int t = threadIdx.x;            // blockDim = 96
    float inv = 1.0f / (float)n;
    float a = 0.f;
#pragma unroll 8
    for (int k = 0; k < HD; k++) a = fmaf(g_colvec[k] * inv, W2[k * HD + t], a);
    hg[t] = a + b2[t];
    __syncthreads();
    if (t < 8) {
        float o = 0.f;
#pragma unroll 8
        for (int k = 0; k < HD; k++) o = fmaf(hg[k], Wr[t * HD + k], o);
        out[t] = o + br[t];
    }
}

// ---------------------------------------------------------------------------
extern "C" void kernel_launch(void* const* d_in, const int* in_sizes, int n_in,
                              void* d_out, int out_size) {
    const float* feat = (const float*)d_in[0];
    const int*   src  = (const int*)d_in[1];
    const int*   dst  = (const int*)d_in[2];
    const float* W1   = (const float*)d_in[3];
    const float* b1   = (const float*)d_in[4];
    const float* W2   = (const float*)d_in[5];
    const float* b2   = (const float*)d_in[6];
    const float* Wr   = (const float*)d_in[7];
    const float* br   = (const float*)d_in[8];
    float* out = (float*)d_out;

    int n = in_sizes[0] / HD;   // 50000
    int e = in_sizes[1];        // 800000

    // Fork s1: GEMM (input-only).
    cudaEventRecord(g_e0, 0);
    cudaStreamWaitEvent(g_s1, g_e0, 0);
    k_gemm1<<<(n + 31) / 32, 256, 0, g_s1>>>(feat, W1, n);
    cudaEventRecord(g_e1, g_s1);

    // s0: edge/build chain.
    k_zero <<<(n + 255) / 256, 256>>>(n);
    k_build<<<(e + 255) / 256, 256>>>(src, dst, e);
    cudaEventRecord(g_eb, 0);

    // Fork s2: norm tables (after build), overlapped with k_c.
    cudaStreamWaitEvent(g_s2, g_eb, 0);
    k_norms<<<(n + 255) / 256, 256, 0, g_s2>>>(n);
    cudaEventRecord(g_en, g_s2);

    k_c<<<(e + 255) / 256, 256>>>(src, dst, e);   // inline norm_in

    // Join, then aggregate + readout.
    cudaStreamWaitEvent(0, g_e1, 0);
    cudaStreamWaitEvent(0, g_en, 0);
    k_agg1 <<<592, 256>>>(b1, n);
    k_final<<<1, HD>>>(W2, b2, Wr, br, out, n);
}